// round 11
// baseline (speedup 1.0000x reference)
#include <cuda_runtime.h>
#include <cuda_fp16.h>
#include <mma.h>
using namespace nvcuda;

#define B_ 64
#define T_ 256
#define C_ 384
#define H_ 6
#define D_ 64
#define M_ (B_*T_)

// Scratch (allocation-free rule: __device__ globals) — fp16
__device__ __align__(16) __half g_qh[B_*H_*T_*D_];   // pre-scaled by 0.125
__device__ __align__(16) __half g_kh[B_*H_*T_*D_];
__device__ __align__(16) __half g_vh[B_*H_*T_*D_];
__device__ __align__(16) __half g_oh[B_*H_*T_*D_];
__device__ __align__(16) __half g_xh[M_*C_];
__device__ __align__(16) __half g_wh[3*H_*C_*D_];
__device__ __align__(16) __half g_wph[C_*C_];

typedef wmma::fragment<wmma::matrix_a, 16, 16, 16, __half, wmma::row_major> HFragA;
typedef wmma::fragment<wmma::matrix_b, 16, 16, 16, __half, wmma::row_major> HFragB;
typedef wmma::fragment<wmma::matrix_b, 16, 16, 16, __half, wmma::col_major> HFragBT;
typedef wmma::fragment<wmma::accumulator, 16, 16, 16, float> HFragC;

__device__ __forceinline__ void cp16(void* sdst, const void* gsrc) {
    unsigned a = (unsigned)__cvta_generic_to_shared(sdst);
    asm volatile("cp.async.cg.shared.global [%0], [%1], 16;" :: "r"(a), "l"(gsrc));
}
__device__ __forceinline__ void cp_commit() { asm volatile("cp.async.commit_group;"); }
template<int N> __device__ __forceinline__ void cp_wait() {
    asm volatile("cp.async.wait_group %0;" :: "n"(N));
}

__device__ __forceinline__ void sth4(__half* dst, float4 v) {
    union { __half2 h[2]; uint2 u; } t;
    t.h[0] = __floats2half2_rn(v.x, v.y);
    t.h[1] = __floats2half2_rn(v.z, v.w);
    *(uint2*)dst = t.u;
}

// Store fp32 16x16 acc fragment as fp16 to global via per-warp smem scratch
__device__ __forceinline__ void frag2half(__half* dst, int ldd, const HFragC& f,
                                          float* sc, int lane, float scale) {
    wmma::store_matrix_sync(sc, f, 20, wmma::mem_row_major);
    __syncwarp();
#pragma unroll
    for (int i = lane; i < 64; i += 32) {
        int r = i >> 2, c4 = i & 3;
        float4 v = *(float4*)&sc[r * 20 + c4 * 4];
        v.x *= scale; v.y *= scale; v.z *= scale; v.w *= scale;
        sth4(&dst[(size_t)r * ldd + c4 * 4], v);
    }
    __syncwarp();
}

// ---------------------------------------------------------------------------
// Prep: one segmented fp32 -> fp16 conversion kernel (x | Wq | Wk | Wv | Wp)
// ---------------------------------------------------------------------------
#define NX4 (M_*C_/4)
#define NW4 (H_*C_*D_/4)
#define NTOT4 (NX4 + 4*NW4)

__global__ void prep_kernel(const float4* __restrict__ x,
                            const float4* __restrict__ wq,
                            const float4* __restrict__ wk,
                            const float4* __restrict__ wv,
                            const float4* __restrict__ wp) {
    int i = blockIdx.x * blockDim.x + threadIdx.x;
    if (i >= NTOT4) return;
    const float4* src;
    uint2* dst;
    int off;
    if (i < NX4) {
        src = x; dst = (uint2*)g_xh; off = i;
    } else {
        int j = i - NX4;
        int seg = j / NW4;
        off = j - seg * NW4;
        if (seg == 0)      { src = wq; dst = (uint2*)(g_wh + 0*(size_t)H_*C_*D_); }
        else if (seg == 1) { src = wk; dst = (uint2*)(g_wh + 1*(size_t)H_*C_*D_); }
        else if (seg == 2) { src = wv; dst = (uint2*)(g_wh + 2*(size_t)H_*C_*D_); }
        else               { src = wp; dst = (uint2*)g_wph; }
    }
    float4 v = src[off];
    union { __half2 h[2]; uint2 u; } t;
    t.h[0] = __floats2half2_rn(v.x, v.y);
    t.h[1] = __floats2half2_rn(v.z, v.w);
    dst[off] = t.u;
}

// ---------------------------------------------------------------------------
// Kernel 1: fused QKV projection. 256 thr (4x2 grid of 32x64 warp tiles),
// CTA 128x128, K-tile 32, 4-stage cp.async pipeline. grid (128, 9).
// ---------------------------------------------------------------------------
#define QKA 40
#define QKB 136
#define QKV_A_H (128*QKA)
#define QKV_B_H (32*QKB)
#define QKV_SCR_OFF (4*(QKV_A_H + QKV_B_H))   // halves
#define QKV_SMEM_BYTES (QKV_SCR_OFF*2 + 8*320*4)

__global__ __launch_bounds__(256) void qkv_kernel() {
    extern __shared__ __half smh[];
    __half* Ah = smh;                  // [4][128][QKA]
    __half* Bh = smh + 4 * QKV_A_H;    // [4][32][QKB]
    float* scr = (float*)(smh + QKV_SCR_OFF);

    const int tid = threadIdx.x;
    const int lane = tid & 31;
    const int wid = tid >> 5;
    const int wr = wid & 3;
    const int wc = wid >> 2;
    const int m0 = blockIdx.x * 128;
    const int by = blockIdx.y;
    const int mat = by / 3;
    const int nb = (by % 3) * 128;
    const __half* Wm = g_wh + (size_t)mat * H_ * C_ * D_;
    __half* outp = (mat == 0 ? g_qh : (mat == 1 ? g_kh : g_vh));
    const float oscale = (mat == 0) ? 0.125f : 1.0f;

    HFragC acc[2][4];
#pragma unroll
    for (int i = 0; i < 2; i++)
#pragma unroll
        for (int j = 0; j < 4; j++) wmma::fill_fragment(acc[i][j], 0.0f);

    auto stage = [&](int k0, int buf) {
        __half* Ab = Ah + buf * QKV_A_H;
        __half* Bb = Bh + buf * QKV_B_H;
#pragma unroll
        for (int i = 0; i < 2; i++) {
            int idx = tid + i * 256;
            int r = idx >> 2, c = idx & 3;
            cp16(&Ab[r * QKA + c * 8], &g_xh[(size_t)(m0 + r) * C_ + k0 + c * 8]);
        }
#pragma unroll
        for (int i = 0; i < 2; i++) {
            int idx = tid + i * 256;
            int r = idx >> 4, c = idx & 15;
            int nm = nb + c * 8;
            int h = nm >> 6, d = nm & 63;
            cp16(&Bb[r * QKB + c * 8], &Wm[(size_t)h * C_ * D_ + (k0 + r) * D_ + d]);
        }
    };

    // 4-stage pipeline: prefetch 3 tiles, commit exactly one group per iter
#pragma unroll
    for (int s = 0; s < 3; s++) { stage(s * 32, s); cp_commit(); }

    for (int kt = 0; kt < 12; kt++) {
        if (kt + 3 < 12) stage((kt + 3) * 32, (kt + 3) & 3);
        cp_commit();
        cp_wait<3>();
        __syncthreads();
        const __half* Ab = Ah + (kt & 3) * QKV_A_H;
        const __half* Bb = Bh + (kt & 3) * QKV_B_H;
#pragma unroll
        for (int kk = 0; kk < 2; kk++) {
            HFragA a[2];
            HFragB b[4];
#pragma unroll
            for (int i = 0; i < 2; i++)
                wmma::load_matrix_sync(a[i], &Ab[(wr * 32 + i * 16) * QKA + kk * 16], QKA);
#pragma unroll
            for (int j = 0; j < 4; j++)
                wmma::load_matrix_sync(b[j], &Bb[(kk * 16) * QKB + wc * 64 + j * 16], QKB);
#pragma unroll
            for (int i = 0; i < 2; i++)
#pragma unroll
                for (int j = 0; j < 4; j++)
                    wmma::mma_sync(acc[i][j], a[i], b[j], acc[i][j]);
        }
        __syncthreads();
    }

    const int b = m0 >> 8, t0 = m0 & 255;
    float* mysc = scr + wid * 320;
#pragma unroll
    for (int i = 0; i < 2; i++)
#pragma unroll
        for (int j = 0; j < 4; j++) {
            int nm = nb + wc * 64 + j * 16;
            int h = nm >> 6, d0 = nm & 63;
            __half* op = outp + (size_t)((b * H_ + h) * T_ + t0 + wr * 32 + i * 16) * D_ + d0;
            frag2half(op, D_, acc[i][j], mysc, lane, oscale);
        }
}

// ---------------------------------------------------------------------------
// Kernel 2: causal attention. 128 thr (2x2 of 32x32 warp tiles), 64-row q
// tile, 2-stage K/V buffers, fp32 S panel + in-place fp16 P. grid (4, 6, 64).
// smem ~99KB -> 2 CTAs/SM.
// ---------------------------------------------------------------------------
#define LDS_ 268
#define AQ_H (64*72)
#define KVBUF_H (64*72)
#define ATTN_S_OFF  ((AQ_H + 2*KVBUF_H)*2)              // bytes
#define ATTN_SCR_OFF (ATTN_S_OFF + 64*LDS_*4)
#define ATTN_SMEM_BYTES (ATTN_SCR_OFF + 4*320*4)

__global__ __launch_bounds__(128) void attn_kernel() {
    extern __shared__ char smc[];
    __half* Qh  = (__half*)smc;                    // 64 x 72
    __half* KV0 = (__half*)smc + AQ_H;             // 64 x 72
    __half* KV1 = KV0 + KVBUF_H;
    float*  Ss  = (float*)(smc + ATTN_S_OFF);      // 64 x LDS_
    __half* Hs  = (__half*)Ss;
    float*  scr = (float*)(smc + ATTN_SCR_OFF);

    const int qt = blockIdx.x;                     // 0..3
    const int h  = blockIdx.y;
    const int b  = blockIdx.z;
    const size_t base = (size_t)((b * H_ + h) * T_) * D_;
    const __half* qp = g_qh + base + (size_t)qt * 64 * D_;
    const __half* kp = g_kh + base;
    const __half* vp = g_vh + base;

    const int tid = threadIdx.x;
    const int lane = tid & 31;
    const int wid = tid >> 5;
    const int wr = wid & 1;
    const int wc = wid >> 1;
    const int kbmax = qt;
    const int L = (qt + 1) * 64;

    auto stageKV = [&](const __half* src, int kb, int buf) {
        __half* Dst = buf ? KV1 : KV0;
#pragma unroll
        for (int i = 0; i < 4; i++) {
            int idx = tid + i * 128;
            int r = idx >> 3, c = idx & 7;
            cp16(&Dst[r * 72 + c * 8], &src[(size_t)(kb * 64 + r) * D_ + c * 8]);
        }
    };

    // Q copy together with K0 in group 1
#pragma unroll
    for (int i = 0; i < 4; i++) {
        int idx = tid + i * 128;
        int r = idx >> 3, c = idx & 7;
        cp16(&Qh[r * 72 + c * 8], &qp[(size_t)r * D_ + c * 8]);
    }
    stageKV(kp, 0, 0);
    cp_commit();

    // Phase 1: S = Q @ K^T
    for (int kb = 0; kb <= kbmax; kb++) {
        if (kb < kbmax) { stageKV(kp, kb + 1, (kb + 1) & 1); cp_commit(); cp_wait<1>(); }
        else cp_wait<0>();
        __syncthreads();
        const __half* Kb = (kb & 1) ? KV1 : KV0;

        HFragC sf[2][2];
#pragma unroll
        for (int i = 0; i < 2; i++)
#pragma unroll
            for (int j = 0; j < 2; j++) wmma::fill_fragment(sf[i][j], 0.0f);
#pragma unroll
        for (int kk = 0; kk < 4; kk++) {
            HFragA a[2];
            HFragBT bt[2];
#pragma unroll
            for (int i = 0; i < 2; i++)
                wmma::load_matrix_sync(a[i], &Qh[(wr * 32 + i * 16) * 72 + kk * 16], 72);
#pragma unroll
            for (int j = 0; j < 2; j++)
                wmma::load_matrix_sync(bt[j], &Kb[(wc * 32 + j * 16) * 72 + kk * 16], 72);
#pragma unroll
            for (int i = 0; i < 2; i++)
#pragma unroll
                for (int j = 0; j < 2; j++)
                    wmma::mma_sync(sf[i][j], a[i], bt[j], sf[i][j]);
        }
#pragma unroll
        for (int i = 0; i < 2; i++)
#pragma unroll
            for (int j = 0; j < 2; j++)
                wmma::store_matrix_sync(
                    &Ss[(wr * 32 + i * 16) * LDS_ + kb * 64 + wc * 32 + j * 16],
                    sf[i][j], LDS_, wmma::mem_row_major);
        __syncthreads();
    }

    // Softmax (fp32, register-held), P -> fp16 in place (16 rows/warp)
    const int nk = L >> 5;
    for (int rr = 0; rr < 16; rr++) {
        int r = wid * 16 + rr;
        int t = qt * 64 + r;
        float* Srow = &Ss[r * LDS_];
        float p[8];
        float mx = -1e30f;
        for (int k = 0; k < nk; k++) {
            int c = lane + 32 * k;
            float s = (c <= t) ? Srow[c] : -1e30f;
            p[k] = s;
            mx = fmaxf(mx, s);
        }
#pragma unroll
        for (int o = 16; o; o >>= 1) mx = fmaxf(mx, __shfl_xor_sync(~0u, mx, o));
        float sum = 0.f;
        for (int k = 0; k < nk; k++) {
            float e = __expf(p[k] - mx);
            p[k] = e;
            sum += e;
        }
#pragma unroll
        for (int o = 16; o; o >>= 1) sum += __shfl_xor_sync(~0u, sum, o);
        float inv = 1.f / sum;
        __half* Hrow = (__half*)Srow;
        for (int k = 0; k < nk; k++)
            Hrow[lane + 32 * k] = __float2half_rn(p[k] * inv);
    }

    // Phase 2: O = P @ V  (prefetch V0 issued before the P-visibility sync)
    stageKV(vp, 0, 0);
    cp_commit();
    __syncthreads();   // P visible to all warps

    HFragC of[2][2];
#pragma unroll
    for (int i = 0; i < 2; i++)
#pragma unroll
        for (int j = 0; j < 2; j++) wmma::fill_fragment(of[i][j], 0.0f);

    for (int kb = 0; kb <= kbmax; kb++) {
        if (kb < kbmax) { stageKV(vp, kb + 1, (kb + 1) & 1); cp_commit(); cp_wait<1>(); }
        else cp_wait<0>();
        __syncthreads();
        const __half* Vb = (kb & 1) ? KV1 : KV0;
#pragma unroll
        for (int kk = 0; kk < 4; kk++) {
            HFragA a[2];
            HFragB bf[2];
#pragma unroll
            for (int i = 0; i < 2; i++)
                wmma::load_matrix_sync(
                    a[i], &Hs[(wr * 32 + i * 16) * (2 * LDS_) + kb * 64 + kk * 16],
                    2 * LDS_);
#pragma unroll
            for (int j = 0; j < 2; j++)
                wmma::load_matrix_sync(bf[j], &Vb[(kk * 16) * 72 + wc * 32 + j * 16], 72);
#pragma unroll
            for (int i = 0; i < 2; i++)
#pragma unroll
                for (int j = 0; j < 2; j++)
                    wmma::mma_sync(of[i][j], a[i], bf[j], of[i][j]);
        }
        __syncthreads();
    }

    __half* op = g_oh + base + (size_t)(qt * 64) * D_;
    float* mysc = scr + wid * 320;
#pragma unroll
    for (int i = 0; i < 2; i++)
#pragma unroll
        for (int j = 0; j < 2; j++)
            frag2half(op + (size_t)(wr * 32 + i * 16) * D_ + wc * 32 + j * 16,
                      D_, of[i][j], mysc, lane, 1.0f);
}

// ---------------------------------------------------------------------------
// Kernel 3: output projection. 128 thr (2x2 of 32x64 warp tiles),
// CTA 64 x 128, K-tile 32, 4-stage cp.async, bias in acc. grid (256, 3).
// ---------------------------------------------------------------------------
#define PA_H (64*QKA)
#define PB_H (32*QKB)
#define PROJ_SMEM_BYTES ((4*(PA_H + PB_H))*2)

__global__ __launch_bounds__(128) void proj_kernel(const float* __restrict__ bp,
                                                   float* __restrict__ out) {
    extern __shared__ __half smh[];
    __half* Ah = smh;               // [4][64][QKA]
    __half* Bh = smh + 4 * PA_H;    // [4][32][QKB]
    float* bias_s = (float*)smh;    // transient [16][136]

    const int tid = threadIdx.x;
    const int wid = tid >> 5;
    const int wr = wid & 1, wc = wid >> 1;
    const int m0 = blockIdx.x * 64;
    const int n0 = blockIdx.y * 128;
    const int b = m0 >> 8, t0 = m0 & 255;

#pragma unroll
    for (int i = 0; i < 4; i++) {
        int idx = tid + i * 128;
        int r = idx >> 5, c4 = idx & 31;
        *(float4*)&bias_s[r * 136 + c4 * 4] = *(const float4*)&bp[n0 + c4 * 4];
    }
    __syncthreads();

    HFragC acc[2][4];
#pragma unroll
    for (int i = 0; i < 2; i++)
#pragma unroll
        for (int j = 0; j < 4; j++)
            wmma::load_matrix_sync(acc[i][j], &bias_s[wc * 64 + j * 16], 136,
                                   wmma::mem_row_major);
    __syncthreads();

    auto stage = [&](int k0, int buf) {
        __half* Ab = Ah + buf * PA_H;
        __half* Bb = Bh + buf * PB_H;
        const int hh = k0 >> 6, d0 = k0 & 63;
#pragma unroll
        for (int i = 0; i < 2; i++) {
            int idx = tid + i * 128;
            int r = idx >> 2, c = idx & 3;
            cp16(&Ab[r * QKA + c * 8],
                 &g_oh[(size_t)((b * H_ + hh) * T_ + t0 + r) * D_ + d0 + c * 8]);
        }
#pragma unroll
        for (int i = 0; i < 4; i++) {
            int idx = tid + i * 128;
            int r = idx >> 4, c = idx & 15;
            cp16(&Bb[r * QKB + c * 8], &g_wph[(size_t)(k0 + r) * C_ + n0 + c * 8]);
        }
    };

#pragma unroll
    for (int s = 0; s < 3; s++) { stage(s * 32, s); cp_commit(); }

    for (int kt = 0; kt < 12; kt++) {
        if (kt + 3 < 12) stage((kt + 3) * 32, (kt + 3) & 3);
        cp_commit();
        cp_wait<3>();
        __syncthreads();
        const __half* Ab = Ah + (kt & 3) * PA_H;
        const __half* Bb = Bh + (kt & 3) * PB_H;
#pragma unroll
        for (int kk = 0; kk < 2; kk++) {
            HFragA a[2];
            HFragB bf[4];
#pragma unroll
            for (int i = 0; i < 2; i++)
                wmma::load_matrix_sync(a[i], &Ab[(wr * 32 + i * 16) * QKA + kk * 16], QKA);
#pragma unroll
            for (int j = 0; j < 4; j++)
                wmma::load_matrix_sync(bf[j], &Bb[(kk * 16) * QKB + wc * 64 + j * 16], QKB);
#pragma unroll
            for (int i = 0; i < 2; i++)
#pragma unroll
                for (int j = 0; j < 4; j++)
                    wmma::mma_sync(acc[i][j], a[i], bf[j], acc[i][j]);
        }
        __syncthreads();
    }

#pragma unroll
    for (int i = 0; i < 2; i++)
#pragma unroll
        for (int j = 0; j < 4; j++) {
            float* op = out + (size_t)(m0 + wr * 32 + i * 16) * C_ + n0 + wc * 64 + j * 16;
            wmma::store_matrix_sync(op, acc[i][j], C_, wmma::mem_row_major);
        }
}

// ---------------------------------------------------------------------------
extern "C" void kernel_launch(void* const* d_in, const int* in_sizes, int n_in,
                              void* d_out, int out_size) {
    const float* x  = (const float*)d_in[0];
    const float* Wq = (const float*)d_in[1];
    const float* Wk = (const float*)d_in[2];
    const float* Wv = (const float*)d_in[3];
    const float* Wp = (const float*)d_in[4];
    const float* bp = (const float*)d_in[5];
    float* out = (float*)d_out;

    cudaFuncSetAttribute(qkv_kernel, cudaFuncAttributeMaxDynamicSharedMemorySize,
                         QKV_SMEM_BYTES);
    cudaFuncSetAttribute(attn_kernel, cudaFuncAttributeMaxDynamicSharedMemorySize,
                         ATTN_SMEM_BYTES);
    cudaFuncSetAttribute(proj_kernel, cudaFuncAttributeMaxDynamicSharedMemorySize,
                         PROJ_SMEM_BYTES);

    prep_kernel<<<(NTOT4 + 255)/256, 256>>>((const float4*)x, (const float4*)Wq,
                                            (const float4*)Wk, (const float4*)Wv,
                                            (const float4*)Wp);
    qkv_kernel<<<dim3(M_ / 128, 9), 256, QKV_SMEM_BYTES>>>();
    attn_kernel<<<dim3(T_ / 64, H_, B_), 128, ATTN_SMEM_BYTES>>>();
    proj_kernel<<<dim3(M_ / 64, C_ / 128), 128, PROJ_SMEM_BYTES>>>(bp, out);
}

// round 13
// speedup vs baseline: 1.0749x; 1.0749x over previous
#include <cuda_runtime.h>
#include <cuda_fp16.h>
#include <mma.h>
using namespace nvcuda;

#define B_ 64
#define T_ 256
#define C_ 384
#define H_ 6
#define D_ 64
#define M_ (B_*T_)

// Scratch (allocation-free rule: __device__ globals) — fp16
__device__ __align__(16) __half g_qh[B_*H_*T_*D_];   // pre-scaled by 0.125
__device__ __align__(16) __half g_kh[B_*H_*T_*D_];
__device__ __align__(16) __half g_vh[B_*H_*T_*D_];
__device__ __align__(16) __half g_oh[B_*H_*T_*D_];
__device__ __align__(16) __half g_xh[M_*C_];
__device__ __align__(16) __half g_wh[3*H_*C_*D_];
__device__ __align__(16) __half g_wph[C_*C_];

typedef wmma::fragment<wmma::matrix_a, 16, 16, 16, __half, wmma::row_major> HFragA;
typedef wmma::fragment<wmma::matrix_b, 16, 16, 16, __half, wmma::row_major> HFragB;
typedef wmma::fragment<wmma::matrix_b, 16, 16, 16, __half, wmma::col_major> HFragBT;
typedef wmma::fragment<wmma::accumulator, 16, 16, 16, float> HFragC;

__device__ __forceinline__ void cp16(void* sdst, const void* gsrc) {
    unsigned a = (unsigned)__cvta_generic_to_shared(sdst);
    asm volatile("cp.async.cg.shared.global [%0], [%1], 16;" :: "r"(a), "l"(gsrc));
}
__device__ __forceinline__ void cp_commit() { asm volatile("cp.async.commit_group;"); }
template<int N> __device__ __forceinline__ void cp_wait() {
    asm volatile("cp.async.wait_group %0;" :: "n"(N));
}

__device__ __forceinline__ void sth4(__half* dst, float4 v) {
    union { __half2 h[2]; uint2 u; } t;
    t.h[0] = __floats2half2_rn(v.x, v.y);
    t.h[1] = __floats2half2_rn(v.z, v.w);
    *(uint2*)dst = t.u;
}

// Store fp32 16x16 acc fragment as fp16 (generic dst) via per-warp smem scratch
__device__ __forceinline__ void frag2half(__half* dst, int ldd, const HFragC& f,
                                          float* sc, int lane, float scale) {
    wmma::store_matrix_sync(sc, f, 20, wmma::mem_row_major);
    __syncwarp();
#pragma unroll
    for (int i = lane; i < 64; i += 32) {
        int r = i >> 2, c4 = i & 3;
        float4 v = *(float4*)&sc[r * 20 + c4 * 4];
        v.x *= scale; v.y *= scale; v.z *= scale; v.w *= scale;
        sth4(&dst[(size_t)r * ldd + c4 * 4], v);
    }
    __syncwarp();
}

// ---------------------------------------------------------------------------
// Prep: one segmented fp32 -> fp16 conversion kernel (x | Wq | Wk | Wv | Wp)
// ---------------------------------------------------------------------------
#define NX4 (M_*C_/4)
#define NW4 (H_*C_*D_/4)
#define NTOT4 (NX4 + 4*NW4)

__global__ void prep_kernel(const float4* __restrict__ x,
                            const float4* __restrict__ wq,
                            const float4* __restrict__ wk,
                            const float4* __restrict__ wv,
                            const float4* __restrict__ wp) {
    int i = blockIdx.x * blockDim.x + threadIdx.x;
    if (i >= NTOT4) return;
    const float4* src;
    uint2* dst;
    int off;
    if (i < NX4) {
        src = x; dst = (uint2*)g_xh; off = i;
    } else {
        int j = i - NX4;
        int seg = j / NW4;
        off = j - seg * NW4;
        if (seg == 0)      { src = wq; dst = (uint2*)(g_wh + 0*(size_t)H_*C_*D_); }
        else if (seg == 1) { src = wk; dst = (uint2*)(g_wh + 1*(size_t)H_*C_*D_); }
        else if (seg == 2) { src = wv; dst = (uint2*)(g_wh + 2*(size_t)H_*C_*D_); }
        else               { src = wp; dst = (uint2*)g_wph; }
    }
    float4 v = src[off];
    union { __half2 h[2]; uint2 u; } t;
    t.h[0] = __floats2half2_rn(v.x, v.y);
    t.h[1] = __floats2half2_rn(v.z, v.w);
    dst[off] = t.u;
}

// ---------------------------------------------------------------------------
// Kernel 1: fused QKV projection (R9 best variant). 256 thr, CTA 128x128,
// K-tile 32, 2-stage cp.async. grid (128, 9).
// ---------------------------------------------------------------------------
#define QKA 40
#define QKB 136
#define QKV_A_H (128*QKA)
#define QKV_B_H (32*QKB)
#define QKV_SCR_OFF (2*(QKV_A_H + QKV_B_H))   // halves
#define QKV_SMEM_BYTES (QKV_SCR_OFF*2 + 8*320*4)

__global__ __launch_bounds__(256) void qkv_kernel() {
    extern __shared__ __half smh[];
    __half* Ah = smh;                  // [2][128][QKA]
    __half* Bh = smh + 2 * QKV_A_H;    // [2][32][QKB]
    float* scr = (float*)(smh + QKV_SCR_OFF);

    const int tid = threadIdx.x;
    const int lane = tid & 31;
    const int wid = tid >> 5;
    const int wr = wid & 3;
    const int wc = wid >> 2;
    const int m0 = blockIdx.x * 128;
    const int by = blockIdx.y;
    const int mat = by / 3;
    const int nb = (by % 3) * 128;
    const __half* Wm = g_wh + (size_t)mat * H_ * C_ * D_;
    __half* outp = (mat == 0 ? g_qh : (mat == 1 ? g_kh : g_vh));
    const float oscale = (mat == 0) ? 0.125f : 1.0f;

    HFragC acc[2][4];
#pragma unroll
    for (int i = 0; i < 2; i++)
#pragma unroll
        for (int j = 0; j < 4; j++) wmma::fill_fragment(acc[i][j], 0.0f);

    auto stage = [&](int k0, int buf) {
        __half* Ab = Ah + buf * QKV_A_H;
        __half* Bb = Bh + buf * QKV_B_H;
#pragma unroll
        for (int i = 0; i < 2; i++) {
            int idx = tid + i * 256;
            int r = idx >> 2, c = idx & 3;
            cp16(&Ab[r * QKA + c * 8], &g_xh[(size_t)(m0 + r) * C_ + k0 + c * 8]);
        }
#pragma unroll
        for (int i = 0; i < 2; i++) {
            int idx = tid + i * 256;
            int r = idx >> 4, c = idx & 15;
            int nm = nb + c * 8;
            int h = nm >> 6, d = nm & 63;
            cp16(&Bb[r * QKB + c * 8], &Wm[(size_t)h * C_ * D_ + (k0 + r) * D_ + d]);
        }
    };

    stage(0, 0);
    cp_commit();

    for (int kt = 0; kt < 12; kt++) {
        const int cur = kt & 1;
        if (kt < 11) { stage((kt + 1) * 32, cur ^ 1); cp_commit(); cp_wait<1>(); }
        else cp_wait<0>();
        __syncthreads();
        const __half* Ab = Ah + cur * QKV_A_H;
        const __half* Bb = Bh + cur * QKV_B_H;
#pragma unroll
        for (int kk = 0; kk < 2; kk++) {
            HFragA a[2];
            HFragB b[4];
#pragma unroll
            for (int i = 0; i < 2; i++)
                wmma::load_matrix_sync(a[i], &Ab[(wr * 32 + i * 16) * QKA + kk * 16], QKA);
#pragma unroll
            for (int j = 0; j < 4; j++)
                wmma::load_matrix_sync(b[j], &Bb[(kk * 16) * QKB + wc * 64 + j * 16], QKB);
#pragma unroll
            for (int i = 0; i < 2; i++)
#pragma unroll
                for (int j = 0; j < 4; j++)
                    wmma::mma_sync(acc[i][j], a[i], b[j], acc[i][j]);
        }
        __syncthreads();
    }

    const int b = m0 >> 8, t0 = m0 & 255;
    float* mysc = scr + wid * 320;
#pragma unroll
    for (int i = 0; i < 2; i++)
#pragma unroll
        for (int j = 0; j < 4; j++) {
            int nm = nb + wc * 64 + j * 16;
            int h = nm >> 6, d0 = nm & 63;
            __half* op = outp + (size_t)((b * H_ + h) * T_ + t0 + wr * 32 + i * 16) * D_ + d0;
            frag2half(op, D_, acc[i][j], mysc, lane, oscale);
        }
}

// ---------------------------------------------------------------------------
// Kernel 2: resident-head causal attention. One CTA per (b,h); Q,K,V for the
// whole head loaded once into smem; 4 causal 64-row q-blocks computed fully
// from smem. 256 thr (8 warps). grid (6, 64).
// ---------------------------------------------------------------------------
#define LDS_ 268
#define AQKV_H (256*72)                               // halves per tensor
#define ATTN_S_OFF  (3*AQKV_H*2)                      // bytes
#define ATTN_SCR_OFF (ATTN_S_OFF + 64*LDS_*4)
#define ATTN_SMEM_BYTES (ATTN_SCR_OFF + 8*320*4)      // ~189.4 KB

__global__ __launch_bounds__(256) void attn_kernel() {
    extern __shared__ char smc[];
    __half* Qs = (__half*)smc;                 // 256 x 72
    __half* Ks = Qs + AQKV_H;                  // 256 x 72
    __half* Vs = Ks + AQKV_H;                  // 256 x 72
    float*  Ss = (float*)(smc + ATTN_S_OFF);   // 64 x LDS_ (reused per q-block)
    __half* Hs = (__half*)Ss;                  // fp16 P view, stride 2*LDS_
    float*  scr = (float*)(smc + ATTN_SCR_OFF);

    const int h = blockIdx.x;
    const int b = blockIdx.y;
    const size_t base = (size_t)((b * H_ + h) * T_) * D_;
    const __half* qp = g_qh + base;
    const __half* kp = g_kh + base;
    const __half* vp = g_vh + base;

    const int tid = threadIdx.x;
    const int lane = tid & 31;
    const int wid = tid >> 5;
    const int wr = wid & 3;        // 16-row group within 64-row q block
    const int wc = wid >> 2;       // half split (0/1)
    float* mysc = scr + wid * 320;

    // Load Q, K, V for the whole head: 3 x 256 rows x 8 uint4
#pragma unroll
    for (int i = 0; i < 8; i++) {
        int idx = tid + i * 256;
        int r = idx >> 3, c = idx & 7;
        cp16(&Qs[r * 72 + c * 8], &qp[(size_t)r * D_ + c * 8]);
        cp16(&Ks[r * 72 + c * 8], &kp[(size_t)r * D_ + c * 8]);
        cp16(&Vs[r * 72 + c * 8], &vp[(size_t)r * D_ + c * 8]);
    }
    cp_commit();
    cp_wait<0>();
    __syncthreads();

    for (int qblk = 0; qblk < 4; qblk++) {
        const int L = (qblk + 1) * 64;

        // ---- S = Q[qblk] @ K^T (64 x L), warps 4 rows x 2 col-halves ----
        HFragA aq[4];
#pragma unroll
        for (int kk = 0; kk < 4; kk++)
            wmma::load_matrix_sync(aq[kk], &Qs[(qblk * 64 + wr * 16) * 72 + kk * 16], 72);

        for (int kb = 0; kb <= qblk; kb++) {
            HFragC sf[2];
#pragma unroll
            for (int j = 0; j < 2; j++) wmma::fill_fragment(sf[j], 0.0f);
#pragma unroll
            for (int kk = 0; kk < 4; kk++) {
#pragma unroll
                for (int j = 0; j < 2; j++) {
                    HFragBT bt;
                    wmma::load_matrix_sync(bt, &Ks[(kb * 64 + wc * 32 + j * 16) * 72 + kk * 16], 72);
                    wmma::mma_sync(sf[j], aq[kk], bt, sf[j]);
                }
            }
#pragma unroll
            for (int j = 0; j < 2; j++)
                wmma::store_matrix_sync(&Ss[(wr * 16) * LDS_ + kb * 64 + wc * 32 + j * 16],
                                        sf[j], LDS_, wmma::mem_row_major);
        }
        __syncthreads();

        // ---- softmax: 8 rows per warp, register-held; P -> fp16 in place ----
        const int nk = (qblk + 1) * 2;
        for (int rr = 0; rr < 8; rr++) {
            int r = wid * 8 + rr;
            int t = qblk * 64 + r;
            float* Srow = &Ss[r * LDS_];
            float p[8];
            float mx = -1e30f;
            for (int k = 0; k < nk; k++) {
                int c = lane + 32 * k;
                float s = (c <= t) ? Srow[c] : -1e30f;
                p[k] = s;
                mx = fmaxf(mx, s);
            }
#pragma unroll
            for (int o = 16; o; o >>= 1) mx = fmaxf(mx, __shfl_xor_sync(~0u, mx, o));
            float sum = 0.f;
            for (int k = 0; k < nk; k++) {
                float e = __expf(p[k] - mx);
                p[k] = e;
                sum += e;
            }
#pragma unroll
            for (int o = 16; o; o >>= 1) sum += __shfl_xor_sync(~0u, sum, o);
            float inv = 1.f / sum;
            __half* Hrow = (__half*)Srow;
            for (int k = 0; k < nk; k++)
                Hrow[lane + 32 * k] = __float2half_rn(p[k] * inv);
        }
        __syncthreads();

        // ---- O[qblk] = P @ V (64 x 64), warps 4 rows x 2 col-halves ----
        HFragC of[2];
#pragma unroll
        for (int j = 0; j < 2; j++) wmma::fill_fragment(of[j], 0.0f);
        for (int kt = 0; kt < (qblk + 1) * 4; kt++) {
            HFragA a;
            wmma::load_matrix_sync(a, &Hs[(wr * 16) * (2 * LDS_) + kt * 16], 2 * LDS_);
#pragma unroll
            for (int j = 0; j < 2; j++) {
                HFragB bf;
                wmma::load_matrix_sync(bf, &Vs[(kt * 16) * 72 + wc * 32 + j * 16], 72);
                wmma::mma_sync(of[j], a, bf, of[j]);
            }
        }

        __half* op = g_oh + base + (size_t)(qblk * 64 + wr * 16) * D_ + wc * 32;
#pragma unroll
        for (int j = 0; j < 2; j++)
            frag2half(op + j * 16, D_, of[j], mysc, lane, 1.0f);
        __syncthreads();   // S buffer reused next q-block
    }
}

// ---------------------------------------------------------------------------
// Kernel 3: output projection (R9 best variant). 128 thr, CTA 64x128,
// K-tile 32, 2-stage cp.async, bias in acc. grid (256, 3).
// ---------------------------------------------------------------------------
#define PA_H (64*QKA)
#define PB_H (32*QKB)
#define PROJ_SMEM_BYTES ((2*(PA_H + PB_H))*2)

__global__ __launch_bounds__(128) void proj_kernel(const float* __restrict__ bp,
                                                   float* __restrict__ out) {
    extern __shared__ __half smh[];
    __half* Ah = smh;               // [2][64][QKA]
    __half* Bh = smh + 2 * PA_H;    // [2][32][QKB]
    float* bias_s = (float*)smh;    // transient [16][136]

    const int tid = threadIdx.x;
    const int wid = tid >> 5;
    const int wr = wid & 1, wc = wid >> 1;
    const int m0 = blockIdx.x * 64;
    const int n0 = blockIdx.y * 128;
    const int b = m0 >> 8, t0 = m0 & 255;

#pragma unroll
    for (int i = 0; i < 4; i++) {
        int idx = tid + i * 128;
        int r = idx >> 5, c4 = idx & 31;
        *(float4*)&bias_s[r * 136 + c4 * 4] = *(const float4*)&bp[n0 + c4 * 4];
    }
    __syncthreads();

    HFragC acc[2][4];
#pragma unroll
    for (int i = 0; i < 2; i++)
#pragma unroll
        for (int j = 0; j < 4; j++)
            wmma::load_matrix_sync(acc[i][j], &bias_s[wc * 64 + j * 16], 136,
                                   wmma::mem_row_major);
    __syncthreads();

    auto stage = [&](int k0, int buf) {
        __half* Ab = Ah + buf * PA_H;
        __half* Bb = Bh + buf * PB_H;
        const int hh = k0 >> 6, d0 = k0 & 63;
#pragma unroll
        for (int i = 0; i < 2; i++) {
            int idx = tid + i * 128;
            int r = idx >> 2, c = idx & 3;
            cp16(&Ab[r * QKA + c * 8],
                 &g_oh[(size_t)((b * H_ + hh) * T_ + t0 + r) * D_ + d0 + c * 8]);
        }
#pragma unroll
        for (int i = 0; i < 4; i++) {
            int idx = tid + i * 128;
            int r = idx >> 4, c = idx & 15;
            cp16(&Bb[r * QKB + c * 8], &g_wph[(size_t)(k0 + r) * C_ + n0 + c * 8]);
        }
    };

    stage(0, 0);
    cp_commit();

    for (int kt = 0; kt < 12; kt++) {
        const int cur = kt & 1;
        if (kt < 11) { stage((kt + 1) * 32, cur ^ 1); cp_commit(); cp_wait<1>(); }
        else cp_wait<0>();
        __syncthreads();
        const __half* Ab = Ah + cur * PA_H;
        const __half* Bb = Bh + cur * PB_H;
#pragma unroll
        for (int kk = 0; kk < 2; kk++) {
            HFragA a[2];
            HFragB bf[4];
#pragma unroll
            for (int i = 0; i < 2; i++)
                wmma::load_matrix_sync(a[i], &Ab[(wr * 32 + i * 16) * QKA + kk * 16], QKA);
#pragma unroll
            for (int j = 0; j < 4; j++)
                wmma::load_matrix_sync(bf[j], &Bb[(kk * 16) * QKB + wc * 64 + j * 16], QKB);
#pragma unroll
            for (int i = 0; i < 2; i++)
#pragma unroll
                for (int j = 0; j < 4; j++)
                    wmma::mma_sync(acc[i][j], a[i], bf[j], acc[i][j]);
        }
        __syncthreads();
    }

#pragma unroll
    for (int i = 0; i < 2; i++)
#pragma unroll
        for (int j = 0; j < 4; j++) {
            float* op = out + (size_t)(m0 + wr * 32 + i * 16) * C_ + n0 + wc * 64 + j * 16;
            wmma::store_matrix_sync(op, acc[i][j], C_, wmma::mem_row_major);
        }
}

// ---------------------------------------------------------------------------
extern "C" void kernel_launch(void* const* d_in, const int* in_sizes, int n_in,
                              void* d_out, int out_size) {
    const float* x  = (const float*)d_in[0];
    const float* Wq = (const float*)d_in[1];
    const float* Wk = (const float*)d_in[2];
    const float* Wv = (const float*)d_in[3];
    const float* Wp = (const float*)d_in[4];
    const float* bp = (const float*)d_in[5];
    float* out = (float*)d_out;

    cudaFuncSetAttribute(qkv_kernel, cudaFuncAttributeMaxDynamicSharedMemorySize,
                         QKV_SMEM_BYTES);
    cudaFuncSetAttribute(attn_kernel, cudaFuncAttributeMaxDynamicSharedMemorySize,
                         ATTN_SMEM_BYTES);
    cudaFuncSetAttribute(proj_kernel, cudaFuncAttributeMaxDynamicSharedMemorySize,
                         PROJ_SMEM_BYTES);

    prep_kernel<<<(NTOT4 + 255)/256, 256>>>((const float4*)x, (const float4*)Wq,
                                            (const float4*)Wk, (const float4*)Wv,
                                            (const float4*)Wp);
    qkv_kernel<<<dim3(M_ / 128, 9), 256, QKV_SMEM_BYTES>>>();
    attn_kernel<<<dim3(H_, B_), 256, ATTN_SMEM_BYTES>>>();
    proj_kernel<<<dim3(M_ / 64, C_ / 128), 128, PROJ_SMEM_BYTES>>>(bp, out);
}